// round 10
// baseline (speedup 1.0000x reference)
#include <cuda_runtime.h>
#include <math.h>
#include <stdint.h>

// Problem constants
#define Bb 128
#define Tt 400
#define Hh 512
#define H2 1024
#define Ee 128
#define Vv 50000

// Output layout (concatenated reference tuple, row-major each)
#define OFF_FINAL 0L
#define OFF_H     6400000L
#define OFF_C     6465536L
#define OFF_CT    6531072L
#define OFF_ATTN  6662144L
#define OFF_PGEN  6713344L
#define OFF_COV   6713472L

// Scratch (device globals: zero-initialized at module load; the tail of
// vsoftmax_scatter_kernel re-zeroes the atomic accumulators so every call
// begins AND ends with zeroed accumulators -> deterministic across replays).
__device__ float g_x[Bb * Ee];
__device__ float g_gates[Bb * 4 * Hh];
__device__ float g_decfea[Bb * H2];
__device__ float g_scores[Bb * Tt];
__device__ float g_o1[Bb * Hh];
__device__ float g_pgacc[Bb];
__device__ float g_logits[(size_t)Bb * Vv];

__device__ __forceinline__ float tanh_fast(float x) {
    float y;
    asm("tanh.approx.f32 %0, %1;" : "=f"(y) : "f"(x));
    return y;
}
__device__ __forceinline__ float sigmoid_fast(float x) {
    return 1.0f / (1.0f + __expf(-x));
}
// pack two fp32 -> bf16x2 register ({lo: v.x, hi: v.y})
__device__ __forceinline__ uint32_t cvt_bf2(float2 v) {
    uint32_t r;
    asm("cvt.rn.bf16x2.f32 %0, %1, %2;" : "=r"(r) : "f"(v.y), "f"(v.x));
    return r;
}

// ---------------------------------------------------------------------------
// Generic small GEMM (FFMA), software-pipelined:
// C[128,N] (+)= A1@W1^T + A2@W2^T + bias, K-split across gridDim.y.
// Global loads for chunk s+1 are issued before computing chunk s (register
// double buffer) so DRAM/L2 latency overlaps the FFMA phase.
// Optional a2_idx: row indirection for A2 (fused embedding gather).
// ---------------------------------------------------------------------------
#define BM 128
#define BN 64
#define BK 16

__global__ __launch_bounds__(256) void gemm_bt(
    const float* __restrict__ A1, int lda1, int K1,
    const float* __restrict__ W1, int ldw1,
    const float* __restrict__ A2, int lda2, int K2,
    const float* __restrict__ W2, int ldw2,
    const int* __restrict__ a2_idx,
    const float* __restrict__ bias1, const float* __restrict__ bias2,
    float* __restrict__ C, int N, int kchunk, int split)
{
    __shared__ __align__(16) float As[BK][BM + 4];
    __shared__ __align__(16) float Ws[BK][BN + 4];

    int tid = threadIdx.x;
    int tx = tid & 15;
    int ty = tid >> 4;
    int bn0 = blockIdx.x * BN;

    int steps_total = (K1 + K2) >> 4;
    int s0 = blockIdx.y * kchunk;
    int s1 = min(s0 + kchunk, steps_total);
    if (s0 >= steps_total) return;

    float acc[8][4];
#pragma unroll
    for (int i = 0; i < 8; i++)
#pragma unroll
        for (int j = 0; j < 4; j++) acc[i][j] = 0.0f;

    int a_row = tid >> 2;
    int a_c4 = (tid & 3) * 4;

    // load global fragments for chunk s into registers
    auto load_frag = [&](int s, float4& va1, float4& va2, float4& vw) {
        int kk = s << 4;
        const float* Ap; int lda; int ko;
        const float* Wp; int ldw;
        bool ind = false;
        if (kk < K1) { Ap = A1; lda = lda1; ko = kk;      Wp = W1; ldw = ldw1; }
        else         { Ap = A2; lda = lda2; ko = kk - K1; Wp = W2; ldw = ldw2;
                       ind = (a2_idx != nullptr); }
        int r1 = a_row;
        int r2 = a_row + 64;
        size_t off1 = ind ? (size_t)a2_idx[r1] * lda : (size_t)r1 * lda;
        size_t off2 = ind ? (size_t)a2_idx[r2] * lda : (size_t)r2 * lda;
        va1 = *(const float4*)&Ap[off1 + ko + a_c4];
        va2 = *(const float4*)&Ap[off2 + ko + a_c4];
        vw = make_float4(0.f, 0.f, 0.f, 0.f);
        if (bn0 + a_row < N)
            vw = *(const float4*)&Wp[(size_t)(bn0 + a_row) * ldw + ko + a_c4];
    };

    float4 va1, va2, vw;
    load_frag(s0, va1, va2, vw);

    for (int s = s0; s < s1; ++s) {
        // stage current chunk into smem (transposed for the compute loop)
        As[a_c4 + 0][a_row] = va1.x; As[a_c4 + 1][a_row] = va1.y;
        As[a_c4 + 2][a_row] = va1.z; As[a_c4 + 3][a_row] = va1.w;
        int r2 = a_row + 64;
        As[a_c4 + 0][r2] = va2.x; As[a_c4 + 1][r2] = va2.y;
        As[a_c4 + 2][r2] = va2.z; As[a_c4 + 3][r2] = va2.w;
        Ws[a_c4 + 0][a_row] = vw.x; Ws[a_c4 + 1][a_row] = vw.y;
        Ws[a_c4 + 2][a_row] = vw.z; Ws[a_c4 + 3][a_row] = vw.w;
        __syncthreads();

        // prefetch next chunk (overlaps with compute below)
        float4 na1 = make_float4(0.f, 0.f, 0.f, 0.f);
        float4 na2 = na1, nw = na1;
        if (s + 1 < s1) load_frag(s + 1, na1, na2, nw);

#pragma unroll
        for (int k = 0; k < BK; k++) {
            float4 a0 = *(const float4*)&As[k][ty * 8];
            float4 a1 = *(const float4*)&As[k][ty * 8 + 4];
            float4 w  = *(const float4*)&Ws[k][tx * 4];
            float am[8] = {a0.x, a0.y, a0.z, a0.w, a1.x, a1.y, a1.z, a1.w};
            float wn[4] = {w.x, w.y, w.z, w.w};
#pragma unroll
            for (int i = 0; i < 8; i++)
#pragma unroll
                for (int j = 0; j < 4; j++) acc[i][j] += am[i] * wn[j];
        }
        __syncthreads();

        va1 = na1; va2 = na2; vw = nw;
    }

    bool addb = (blockIdx.y == 0);
#pragma unroll
    for (int i = 0; i < 8; i++) {
        int m = ty * 8 + i;
#pragma unroll
        for (int j = 0; j < 4; j++) {
            int n = bn0 + tx * 4 + j;
            if (n < N) {
                float v = acc[i][j];
                if (addb) {
                    if (bias1) v += bias1[n];
                    if (bias2) v += bias2[n];
                }
                if (split) atomicAdd(&C[(size_t)m * N + n], v);
                else       C[(size_t)m * N + n] = v;
            }
        }
    }
}

// ---------------------------------------------------------------------------
// Vocab GEMM: bf16 m16n8k16 MMA + 4-stage cp.async fp32 pipeline.
// logits[128, 50000] = o1[128,512] @ W_o2[50000,512]^T + b_o2
// ---------------------------------------------------------------------------
#define VG_LDS 24
#define VG_STAGEF (128 * VG_LDS)
#define VG_STAGEB (VG_STAGEF * 4)
#define VG_STAGES 4
#define VG_SMEM_BYTES (VG_STAGES * VG_STAGEB * 2)   // 98304

__device__ __forceinline__ uint32_t smem_u32(const void* p) {
    return (uint32_t)__cvta_generic_to_shared(p);
}

__device__ __forceinline__ void vg_prefetch(
    int s, int stage, const float* __restrict__ A, const float* __restrict__ W,
    int bn0, uint32_t sA, uint32_t sW)
{
    int ck = s * 16;
    int tid = threadIdx.x;
#pragma unroll
    for (int i = 0; i < 2; i++) {
        int slot = i * 256 + tid;
        int row = slot >> 2;
        int c4 = (slot & 3) << 2;
        uint32_t soff = (uint32_t)(stage * VG_STAGEB + (row * VG_LDS + c4) * 4);
        asm volatile("cp.async.cg.shared.global [%0], [%1], 16;"
                     :: "r"(sA + soff), "l"(A + row * 512 + ck + c4) : "memory");
        int nrow = bn0 + row;
        if (nrow < Vv)
            asm volatile("cp.async.cg.shared.global [%0], [%1], 16;"
                         :: "r"(sW + soff), "l"(W + (size_t)nrow * 512 + ck + c4) : "memory");
    }
    asm volatile("cp.async.commit_group;" ::: "memory");
}

__global__ __launch_bounds__(256) void vocab_gemm_mma(
    const float* __restrict__ A, const float* __restrict__ W,
    const float* __restrict__ bias, float* __restrict__ Cl)
{
    extern __shared__ __align__(16) float vgsm[];
    float* As = vgsm;
    float* Ws = vgsm + VG_STAGES * VG_STAGEF;

    int tid = threadIdx.x;
    int lane = tid & 31;
    int wid = tid >> 5;
    int wm = (wid & 1) * 64;
    int wn = (wid >> 1) * 32;
    int bn0 = blockIdx.x * 128;

    int grp = lane >> 2;
    int qid = lane & 3;

    uint32_t sA = smem_u32(As);
    uint32_t sW = smem_u32(Ws);

    if (bn0 + 128 > Vv) {
#pragma unroll
        for (int st = 0; st < VG_STAGES; st++)
            for (int slot = tid; slot < 512; slot += 256) {
                int row = slot >> 2;
                int c4 = (slot & 3) << 2;
                if (bn0 + row >= Vv)
                    *(float4*)&Ws[st * VG_STAGEF + row * VG_LDS + c4] =
                        make_float4(0.f, 0.f, 0.f, 0.f);
            }
        __syncthreads();
    }

    float acc[4][4][4];
#pragma unroll
    for (int i = 0; i < 4; i++)
#pragma unroll
        for (int j = 0; j < 4; j++)
#pragma unroll
            for (int r = 0; r < 4; r++) acc[i][j][r] = 0.0f;

    vg_prefetch(0, 0, A, W, bn0, sA, sW);
    vg_prefetch(1, 1, A, W, bn0, sA, sW);
    vg_prefetch(2, 2, A, W, bn0, sA, sW);

    for (int s = 0; s < 32; s++) {
        int stage = s & 3;
        if (s < 29) {
            vg_prefetch(s + 3, (s + 3) & 3, A, W, bn0, sA, sW);
            asm volatile("cp.async.wait_group 3;" ::: "memory");
        } else if (s == 29) {
            asm volatile("cp.async.wait_group 2;" ::: "memory");
        } else if (s == 30) {
            asm volatile("cp.async.wait_group 1;" ::: "memory");
        } else {
            asm volatile("cp.async.wait_group 0;" ::: "memory");
        }
        __syncthreads();

        const float* as = As + stage * VG_STAGEF;
        const float* ws = Ws + stage * VG_STAGEF;

        uint32_t af[4][4];
#pragma unroll
        for (int t = 0; t < 4; t++) {
            int r0 = wm + t * 16 + grp;
            const float* b0 = as + r0 * VG_LDS;
            const float* b1 = as + (r0 + 8) * VG_LDS;
            af[t][0] = cvt_bf2(*(const float2*)(b0 + 2 * qid));
            af[t][1] = cvt_bf2(*(const float2*)(b1 + 2 * qid));
            af[t][2] = cvt_bf2(*(const float2*)(b0 + 8 + 2 * qid));
            af[t][3] = cvt_bf2(*(const float2*)(b1 + 8 + 2 * qid));
        }
        uint32_t bf[4][2];
#pragma unroll
        for (int t = 0; t < 4; t++) {
            int n0 = wn + t * 8 + grp;
            const float* b = ws + n0 * VG_LDS;
            bf[t][0] = cvt_bf2(*(const float2*)(b + 2 * qid));
            bf[t][1] = cvt_bf2(*(const float2*)(b + 8 + 2 * qid));
        }
#pragma unroll
        for (int i = 0; i < 4; i++)
#pragma unroll
            for (int j = 0; j < 4; j++) {
                asm volatile(
                    "mma.sync.aligned.m16n8k16.row.col.f32.bf16.bf16.f32 "
                    "{%0,%1,%2,%3}, {%4,%5,%6,%7}, {%8,%9}, {%0,%1,%2,%3};"
                    : "+f"(acc[i][j][0]), "+f"(acc[i][j][1]),
                      "+f"(acc[i][j][2]), "+f"(acc[i][j][3])
                    : "r"(af[i][0]), "r"(af[i][1]), "r"(af[i][2]), "r"(af[i][3]),
                      "r"(bf[j][0]), "r"(bf[j][1]));
            }
        __syncthreads();
    }

#pragma unroll
    for (int i = 0; i < 4; i++) {
        int m0 = wm + i * 16 + grp;
#pragma unroll
        for (int j = 0; j < 4; j++) {
            int n = bn0 + wn + j * 8 + 2 * qid;
            if (n < Vv) {
                float2 b2 = *(const float2*)&bias[n];
                float2 v0 = make_float2(acc[i][j][0] + b2.x, acc[i][j][1] + b2.y);
                float2 v1 = make_float2(acc[i][j][2] + b2.x, acc[i][j][3] + b2.y);
                *(float2*)&Cl[(size_t)m0 * Vv + n] = v0;
                *(float2*)&Cl[(size_t)(m0 + 8) * Vv + n] = v1;
            }
        }
    }
}

// ---------------------------------------------------------------------------
// LSTM elementwise (float4 vectorized)
// ---------------------------------------------------------------------------
__global__ void lstm_kernel(const float* __restrict__ gates, const float* __restrict__ c0,
                            float* __restrict__ out) {
    int q = blockIdx.x * blockDim.x + threadIdx.x;
    if (q >= Bb * Hh / 4) return;
    int b = q >> 7;
    int h4 = (q & 127) << 2;
    const float* g = gates + (size_t)b * 4 * Hh;
    float4 gi = *(const float4*)&g[h4];
    float4 gf = *(const float4*)&g[512 + h4];
    float4 gg = *(const float4*)&g[1024 + h4];
    float4 go = *(const float4*)&g[1536 + h4];
    float4 cp = *(const float4*)&c0[(size_t)b * Hh + h4];
    float4 c, hh;
    c.x = sigmoid_fast(gf.x) * cp.x + sigmoid_fast(gi.x) * tanhf(gg.x);
    c.y = sigmoid_fast(gf.y) * cp.y + sigmoid_fast(gi.y) * tanhf(gg.y);
    c.z = sigmoid_fast(gf.z) * cp.z + sigmoid_fast(gi.z) * tanhf(gg.z);
    c.w = sigmoid_fast(gf.w) * cp.w + sigmoid_fast(gi.w) * tanhf(gg.w);
    hh.x = sigmoid_fast(go.x) * tanhf(c.x);
    hh.y = sigmoid_fast(go.y) * tanhf(c.y);
    hh.z = sigmoid_fast(go.z) * tanhf(c.z);
    hh.w = sigmoid_fast(go.w) * tanhf(c.w);
    *(float4*)&out[OFF_H + (size_t)b * Hh + h4] = hh;
    *(float4*)&out[OFF_C + (size_t)b * Hh + h4] = c;
}

// ---------------------------------------------------------------------------
// Attention scores
// ---------------------------------------------------------------------------
__global__ __launch_bounds__(256) void scores_kernel(
    const float* __restrict__ ef, const float* __restrict__ dec,
    const float* __restrict__ vw, const float* __restrict__ Wc,
    const float* __restrict__ cov, float* __restrict__ scores)
{
    __shared__ __align__(16) float s_dec[H2];
    __shared__ __align__(16) float s_v[H2];
    __shared__ __align__(16) float s_wc[H2];
    int b = blockIdx.y;
    int tid = threadIdx.x;
    for (int i = tid; i < H2; i += 256) {
        s_dec[i] = dec[(size_t)b * H2 + i];
        s_v[i] = vw[i];
        s_wc[i] = Wc[i];
    }
    __syncthreads();

    int warp = tid >> 5, lane = tid & 31;
    int t = blockIdx.x * 8 + warp;
    float cv = cov[(size_t)b * Tt + t];
    const float* p = ef + ((size_t)b * Tt + t) * H2;

    float acc = 0.0f;
#pragma unroll
    for (int i = 0; i < 8; i++) {
        int n = i * 128 + lane * 4;
        float4 e4 = *(const float4*)(p + n);
        acc += tanh_fast(e4.x + s_dec[n]     + cv * s_wc[n])     * s_v[n];
        acc += tanh_fast(e4.y + s_dec[n + 1] + cv * s_wc[n + 1]) * s_v[n + 1];
        acc += tanh_fast(e4.z + s_dec[n + 2] + cv * s_wc[n + 2]) * s_v[n + 2];
        acc += tanh_fast(e4.w + s_dec[n + 3] + cv * s_wc[n + 3]) * s_v[n + 3];
    }
#pragma unroll
    for (int o = 16; o > 0; o >>= 1) acc += __shfl_down_sync(0xffffffffu, acc, o);
    if (lane == 0) scores[(size_t)b * Tt + t] = acc;
}

// ---------------------------------------------------------------------------
// Fused attention: softmax over T (+mask renorm +coverage), half of c_t,
// partial p_gen dot (atomicAdd into g_pgacc).
// grid = (2, 128), 512 threads.
// ---------------------------------------------------------------------------
__global__ __launch_bounds__(512) void attn_fused_kernel(
    const float* __restrict__ scores, const float* __restrict__ mask,
    const float* __restrict__ cov, const float* __restrict__ eo,
    const float* __restrict__ x, const float* __restrict__ Wpg,
    float* __restrict__ pgacc, float* __restrict__ out)
{
    __shared__ float red[512];
    __shared__ float sa[Tt];

    int b = blockIdx.y, hx = blockIdx.x, tid = threadIdx.x;

    float s = (tid < Tt) ? scores[(size_t)b * Tt + tid] : -1e30f;
    red[tid] = s; __syncthreads();
    for (int st = 256; st > 0; st >>= 1) {
        if (tid < st) red[tid] = fmaxf(red[tid], red[tid + st]);
        __syncthreads();
    }
    float m = red[0]; __syncthreads();

    float e = (tid < Tt) ? __expf(s - m) : 0.0f;
    red[tid] = e; __syncthreads();
    for (int st = 256; st > 0; st >>= 1) {
        if (tid < st) red[tid] += red[tid + st];
        __syncthreads();
    }
    float S = red[0]; __syncthreads();

    float a = (tid < Tt) ? (e / S) * mask[(size_t)b * Tt + tid] : 0.0f;
    red[tid] = a; __syncthreads();
    for (int st = 256; st > 0; st >>= 1) {
        if (tid < st) red[tid] += red[tid + st];
        __syncthreads();
    }
    float S2 = red[0] + 1e-12f;

    float attn = a / S2;
    if (tid < Tt) {
        sa[tid] = attn;
        if (hx == 0) {
            out[OFF_ATTN + (size_t)b * Tt + tid] = attn;
            out[OFF_COV  + (size_t)b * Tt + tid] = cov[(size_t)b * Tt + tid] + attn;
        }
    }
    __syncthreads();

    int n = hx * 512 + tid;
    const float* p = eo + (size_t)b * Tt * H2 + n;
    float acc = 0.0f;
#pragma unroll 16
    for (int t = 0; t < Tt; t++) acc += sa[t] * p[(size_t)t * H2];
    out[OFF_CT + (size_t)b * H2 + n] = acc;

    float pacc = acc * Wpg[n];
    if (hx == 0) {
        pacc += out[OFF_H + (size_t)b * Hh + tid] * Wpg[1024 + tid];
        if (tid < Ee) pacc += x[(size_t)b * Ee + tid] * Wpg[2048 + tid];
    } else {
        pacc += out[OFF_C + (size_t)b * Hh + tid] * Wpg[1536 + tid];
    }
    red[tid] = pacc; __syncthreads();
    for (int st = 256; st > 0; st >>= 1) {
        if (tid < st) red[tid] += red[tid + st];
        __syncthreads();
    }
    if (tid == 0) atomicAdd(&pgacc[b], red[0]);
}

// ---------------------------------------------------------------------------
// Fused vocab softmax (online, float4) + p_gen finalize + pointer scatter
// + scratch-accumulator re-zero (keeps call-start invariant: all zeroed).
// grid = 128, 1024 threads. Vv = 50000 = 12500 float4 exactly.
// ---------------------------------------------------------------------------
__global__ __launch_bounds__(1024) void vsoftmax_scatter_kernel(
    const float* __restrict__ logits, const int* __restrict__ ebev,
    const float* __restrict__ pgacc, const float* __restrict__ bpg,
    float* __restrict__ gx, float* __restrict__ ggates,
    float* __restrict__ gdec, float* __restrict__ go1, float* __restrict__ gpg,
    float* __restrict__ out)
{
    __shared__ float smx[1024];
    __shared__ float ssm[1024];
    int b = blockIdx.x, tid = threadIdx.x;
    const float4* L4 = (const float4*)(logits + (size_t)b * Vv);

    float m = -1e30f, s = 0.0f;
    for (int j = tid; j < Vv / 4; j += 1024) {
        float4 v = L4[j];
        float m4 = fmaxf(fmaxf(v.x, v.y), fmaxf(v.z, v.w));
        float nm = fmaxf(m, m4);
        s = s * __expf(m - nm) + __expf(v.x - nm) + __expf(v.y - nm)
          + __expf(v.z - nm) + __expf(v.w - nm);
        m = nm;
    }
    smx[tid] = m; ssm[tid] = s; __syncthreads();
    for (int st = 512; st > 0; st >>= 1) {
        if (tid < st) {
            float m2 = smx[tid + st], s2 = ssm[tid + st];
            float m1 = smx[tid],      s1 = ssm[tid];
            float nm = fmaxf(m1, m2);
            ssm[tid] = s1 * __expf(m1 - nm) + s2 * __expf(m2 - nm);
            smx[tid] = nm;
        }
        __syncthreads();
    }
    float M = smx[0], S = ssm[0];

    float pg = sigmoid_fast(pgacc[b] + bpg[0]);
    if (tid == 0) out[OFF_PGEN + b] = pg;

    float scale = pg / S;
    float4* F4 = (float4*)(out + (size_t)b * Vv);
    for (int j = tid; j < Vv / 4; j += 1024) {
        float4 v = L4[j];
        float4 w;
        w.x = __expf(v.x - M) * scale;
        w.y = __expf(v.y - M) * scale;
        w.z = __expf(v.z - M) * scale;
        w.w = __expf(v.w - M) * scale;
        F4[j] = w;
    }
    __syncthreads();

    // scatter
    if (tid < Tt) {
        float a = out[OFF_ATTN + (size_t)b * Tt + tid];
        atomicAdd(&out[(size_t)b * Vv + ebev[(size_t)b * Tt + tid]], (1.0f - pg) * a);
    }

    // re-zero atomic accumulators for the next call (grid-stride)
    int gi = b * 1024 + tid;
    int gs = 128 * 1024;
    for (int j = gi; j < Bb * Ee; j += gs) gx[j] = 0.0f;
    for (int j = gi; j < Bb * 4 * Hh; j += gs) ggates[j] = 0.0f;
    for (int j = gi; j < Bb * H2; j += gs) gdec[j] = 0.0f;
    for (int j = gi; j < Bb * Hh; j += gs) go1[j] = 0.0f;
    if (gi < Bb) gpg[gi] = 0.0f;
}

// ---------------------------------------------------------------------------
// Host launch
// ---------------------------------------------------------------------------
static void launch_gemm(const float* A1, int lda1, int K1, const float* W1, int ldw1,
                        const float* A2, int lda2, int K2, const float* W2, int ldw2,
                        const int* a2_idx,
                        const float* b1, const float* b2, float* C, int N, int ksplit)
{
    int steps = (K1 + K2) >> 4;
    int kchunk = (steps + ksplit - 1) / ksplit;
    int ky = (steps + kchunk - 1) / kchunk;
    dim3 grid((N + BN - 1) / BN, ky);
    gemm_bt<<<grid, 256>>>(A1, lda1, K1, W1, ldw1, A2, lda2, K2, W2, ldw2,
                           a2_idx, b1, b2, C, N, kchunk, (ky > 1) ? 1 : 0);
}

extern "C" void kernel_launch(void* const* d_in, const int* in_sizes, int n_in,
                              void* d_out_v, int out_size)
{
    (void)in_sizes; (void)n_in; (void)out_size;
    const int*   y    = (const int*)  d_in[0];
    const float* h0   = (const float*)d_in[1];
    const float* c0   = (const float*)d_in[2];
    const float* ct1  = (const float*)d_in[3];
    const float* eo   = (const float*)d_in[4];
    const float* ef   = (const float*)d_in[5];
    const float* mask = (const float*)d_in[6];
    const int*   ebev = (const int*)  d_in[7];
    const float* cov  = (const float*)d_in[8];
    const float* emb  = (const float*)d_in[9];
    const float* W_c  = (const float*)d_in[10];
    const float* W_dp = (const float*)d_in[11];
    const float* b_dp = (const float*)d_in[12];
    const float* v_w  = (const float*)d_in[13];
    const float* W_xc = (const float*)d_in[14];
    const float* b_xc = (const float*)d_in[15];
    const float* W_ih = (const float*)d_in[16];
    const float* W_hh = (const float*)d_in[17];
    const float* b_ih = (const float*)d_in[18];
    const float* b_hh = (const float*)d_in[19];
    const float* W_pg = (const float*)d_in[20];
    const float* b_pg = (const float*)d_in[21];
    const float* W_o1 = (const float*)d_in[22];
    const float* b_o1 = (const float*)d_in[23];
    const float* W_o2 = (const float*)d_in[24];
    const float* b_o2 = (const float*)d_in[25];
    float* out = (float*)d_out_v;

    float *p_x, *p_gates, *p_dec, *p_scores, *p_o1, *p_logits, *p_pgacc;
    cudaGetSymbolAddress((void**)&p_x,      g_x);
    cudaGetSymbolAddress((void**)&p_gates,  g_gates);
    cudaGetSymbolAddress((void**)&p_dec,    g_decfea);
    cudaGetSymbolAddress((void**)&p_scores, g_scores);
    cudaGetSymbolAddress((void**)&p_o1,     g_o1);
    cudaGetSymbolAddress((void**)&p_logits, g_logits);
    cudaGetSymbolAddress((void**)&p_pgacc,  g_pgacc);

    cudaFuncSetAttribute(vocab_gemm_mma, cudaFuncAttributeMaxDynamicSharedMemorySize,
                         VG_SMEM_BYTES);

    // Accumulators are zero here (module-load init + re-zero in step 9 tail).

    // 1. x = [c_t_1 | emb[y]] @ W_xc^T + b_xc  (grid 144)
    launch_gemm(ct1, H2, H2, W_xc, 1152,
                emb, Ee, Ee, W_xc + 1024, 1152, y,
                b_xc, nullptr, p_x, Ee, 72);

    // 2. gates = x @ W_ih^T + h0 @ W_hh^T + b_ih + b_hh  (grid 256)
    launch_gemm(p_x, Ee, Ee, W_ih, Ee,
                h0, Hh, Hh, W_hh, Hh, nullptr,
                b_ih, b_hh, p_gates, 4 * Hh, 8);

    // 3. LSTM cell
    lstm_kernel<<<(Bb * Hh / 4 + 255) / 256, 256>>>(p_gates, c0, out);

    // 4. dec_fea = [h | c] @ W_dp^T + b_dp  (grid 256)
    launch_gemm(out + OFF_H, Hh, Hh, W_dp, H2,
                out + OFF_C, Hh, Hh, W_dp + 512, H2, nullptr,
                b_dp, nullptr, p_dec, H2, 16);

    // 5. attention scores
    scores_kernel<<<dim3(Tt / 8, Bb), 256>>>(ef, p_dec, v_w, W_c, cov, p_scores);

    // 6. fused softmax + c_t halves + partial p_gen
    attn_fused_kernel<<<dim3(2, Bb), 512>>>(p_scores, mask, cov, eo, p_x, W_pg,
                                            p_pgacc, out);

    // 7. o1 = [h | c_t] @ W_o1^T + b_o1  (grid 256)
    launch_gemm(out + OFF_H, Hh, Hh, W_o1, 3 * Hh,
                out + OFF_CT, H2, H2, W_o1 + 512, 3 * Hh, nullptr,
                b_o1, nullptr, p_o1, Hh, 32);

    // 8. logits via bf16 m16n8k16 MMA GEMM, 4-stage cp.async pipeline
    vocab_gemm_mma<<<(Vv + 127) / 128, 256, VG_SMEM_BYTES>>>(p_o1, W_o2, b_o2, p_logits);

    // 9. fused vocab softmax + p_gen finalize + scatter + accumulator re-zero
    vsoftmax_scatter_kernel<<<Bb, 1024>>>(p_logits, ebev, p_pgacc, b_pg,
                                          p_x, p_gates, p_dec, p_o1, p_pgacc, out);
}

// round 11
// speedup vs baseline: 1.1169x; 1.1169x over previous
#include <cuda_runtime.h>
#include <math.h>
#include <stdint.h>

// Problem constants
#define Bb 128
#define Tt 400
#define Hh 512
#define H2 1024
#define Ee 128
#define Vv 50000

// Output layout (concatenated reference tuple, row-major each)
#define OFF_FINAL 0L
#define OFF_H     6400000L
#define OFF_C     6465536L
#define OFF_CT    6531072L
#define OFF_ATTN  6662144L
#define OFF_PGEN  6713344L
#define OFF_COV   6713472L

// Scratch (device globals: zero-initialized at module load; the tail of
// vsoftmax_scatter_kernel re-zeroes the atomic accumulators so every call
// begins AND ends with zeroed accumulators -> deterministic across replays).
__device__ float g_x[Bb * Ee];
__device__ float g_gates[Bb * 4 * Hh];
__device__ float g_decfea[Bb * H2];
__device__ float g_scores[Bb * Tt];
__device__ float g_o1[Bb * Hh];
__device__ float g_pgacc[Bb];
__device__ float g_logits[(size_t)Bb * Vv];

__device__ __forceinline__ float tanh_fast(float x) {
    float y;
    asm("tanh.approx.f32 %0, %1;" : "=f"(y) : "f"(x));
    return y;
}
__device__ __forceinline__ float sigmoid_fast(float x) {
    return 1.0f / (1.0f + __expf(-x));
}
// pack two fp32 -> bf16x2 register ({lo: v.x, hi: v.y})
__device__ __forceinline__ uint32_t cvt_bf2(float2 v) {
    uint32_t r;
    asm("cvt.rn.bf16x2.f32 %0, %1, %2;" : "=r"(r) : "f"(v.y), "f"(v.x));
    return r;
}
__device__ __forceinline__ uint32_t smem_u32(const void* p) {
    return (uint32_t)__cvta_generic_to_shared(p);
}

// ---------------------------------------------------------------------------
// Small GEMM on tensor cores (tf32 m16n8k8, raw fp32 bits):
// C[128, N] (+)= [A1 | A2] @ [W1 | W2]^T + bias1 + bias2
// CTA tile 128 x 128, BK=16, 4-stage cp.async pipeline, K-split across
// gridDim.y with atomicAdd epilogue (C pre-zeroed). N must be a multiple
// of 128. Optional a2_idx: row indirection for A2 (fused embedding gather).
// K1, K2 multiples of 16.
// ---------------------------------------------------------------------------
#define SG_LDS 20
#define SG_STAGEF (128 * SG_LDS)
#define SG_STAGEB (SG_STAGEF * 4)
#define SG_STAGES 4
#define SG_SMEM_BYTES (SG_STAGES * SG_STAGEB * 2)   // 81920

__global__ __launch_bounds__(256) void small_gemm_mma(
    const float* __restrict__ A1, int lda1, int K1,
    const float* __restrict__ W1, int ldw1,
    const float* __restrict__ A2, int lda2, int K2,
    const float* __restrict__ W2, int ldw2,
    const int* __restrict__ a2_idx,
    const float* __restrict__ bias1, const float* __restrict__ bias2,
    float* __restrict__ C, int N, int kchunk, int split)
{
    extern __shared__ __align__(16) float sgsm[];
    float* As = sgsm;
    float* Ws = sgsm + SG_STAGES * SG_STAGEF;

    int tid = threadIdx.x;
    int lane = tid & 31;
    int wid = tid >> 5;
    int wm = (wid & 1) * 64;
    int wn = (wid >> 1) * 32;
    int bn0 = blockIdx.x * 128;
    int grp = lane >> 2;
    int qid = lane & 3;

    uint32_t sA = smem_u32(As);
    uint32_t sW = smem_u32(Ws);

    int steps_total = (K1 + K2) >> 4;
    int s0 = blockIdx.y * kchunk;
    int s1 = min(s0 + kchunk, steps_total);
    if (s0 >= steps_total) return;
    int nc = s1 - s0;

    auto prefetch = [&](int s, int stage) {
        int kk = s << 4;
        const float* Ap; int lda; int ko;
        const float* Wp; int ldw;
        bool ind = false;
        if (kk < K1) { Ap = A1; lda = lda1; ko = kk;      Wp = W1; ldw = ldw1; }
        else         { Ap = A2; lda = lda2; ko = kk - K1; Wp = W2; ldw = ldw2;
                       ind = (a2_idx != nullptr); }
#pragma unroll
        for (int i = 0; i < 2; i++) {
            int slot = i * 256 + tid;       // 0..511
            int row = slot >> 2;            // 0..127
            int c4 = (slot & 3) << 2;       // 0,4,8,12
            uint32_t soff = (uint32_t)(stage * SG_STAGEB + (row * SG_LDS + c4) * 4);
            size_t aoff = ind ? (size_t)a2_idx[row] * lda : (size_t)row * lda;
            asm volatile("cp.async.cg.shared.global [%0], [%1], 16;"
                         :: "r"(sA + soff), "l"(Ap + aoff + ko + c4) : "memory");
            asm volatile("cp.async.cg.shared.global [%0], [%1], 16;"
                         :: "r"(sW + soff), "l"(Wp + (size_t)(bn0 + row) * ldw + ko + c4)
                         : "memory");
        }
        asm volatile("cp.async.commit_group;" ::: "memory");
    };

    float acc[4][4][4];
#pragma unroll
    for (int i = 0; i < 4; i++)
#pragma unroll
        for (int j = 0; j < 4; j++)
#pragma unroll
            for (int r = 0; r < 4; r++) acc[i][j][r] = 0.0f;

    int committed = 0;
    for (; committed < nc && committed < 3; committed++)
        prefetch(s0 + committed, committed & 3);

    for (int s = 0; s < nc; s++) {
        if (committed < nc) { prefetch(s0 + committed, committed & 3); committed++; }
        int allow = committed - s - 1;     // groups allowed still in flight
        if (allow <= 0)      asm volatile("cp.async.wait_group 0;" ::: "memory");
        else if (allow == 1) asm volatile("cp.async.wait_group 1;" ::: "memory");
        else if (allow == 2) asm volatile("cp.async.wait_group 2;" ::: "memory");
        else                 asm volatile("cp.async.wait_group 3;" ::: "memory");
        __syncthreads();

        const float* as = As + (s & 3) * SG_STAGEF;
        const float* ws = Ws + (s & 3) * SG_STAGEF;

#pragma unroll
        for (int k8 = 0; k8 < 2; k8++) {
            int kk = k8 * 8;
            uint32_t af[4][4];
#pragma unroll
            for (int t = 0; t < 4; t++) {
                int r0 = wm + t * 16 + grp;
                af[t][0] = __float_as_uint(as[r0 * SG_LDS + kk + qid]);
                af[t][1] = __float_as_uint(as[(r0 + 8) * SG_LDS + kk + qid]);
                af[t][2] = __float_as_uint(as[r0 * SG_LDS + kk + qid + 4]);
                af[t][3] = __float_as_uint(as[(r0 + 8) * SG_LDS + kk + qid + 4]);
            }
            uint32_t bf[4][2];
#pragma unroll
            for (int t = 0; t < 4; t++) {
                int n0 = wn + t * 8 + grp;
                bf[t][0] = __float_as_uint(ws[n0 * SG_LDS + kk + qid]);
                bf[t][1] = __float_as_uint(ws[n0 * SG_LDS + kk + qid + 4]);
            }
#pragma unroll
            for (int i = 0; i < 4; i++)
#pragma unroll
                for (int j = 0; j < 4; j++) {
                    asm volatile(
                        "mma.sync.aligned.m16n8k8.row.col.f32.tf32.tf32.f32 "
                        "{%0,%1,%2,%3}, {%4,%5,%6,%7}, {%8,%9}, {%0,%1,%2,%3};"
                        : "+f"(acc[i][j][0]), "+f"(acc[i][j][1]),
                          "+f"(acc[i][j][2]), "+f"(acc[i][j][3])
                        : "r"(af[i][0]), "r"(af[i][1]), "r"(af[i][2]), "r"(af[i][3]),
                          "r"(bf[j][0]), "r"(bf[j][1]));
                }
        }
        __syncthreads();
    }

    bool addb = (blockIdx.y == 0);
#pragma unroll
    for (int i = 0; i < 4; i++) {
        int m0 = wm + i * 16 + grp;
#pragma unroll
        for (int j = 0; j < 4; j++) {
            int n = bn0 + wn + j * 8 + 2 * qid;
            float b0 = 0.0f, b1 = 0.0f;
            if (addb) {
                if (bias1) { b0 += bias1[n]; b1 += bias1[n + 1]; }
                if (bias2) { b0 += bias2[n]; b1 += bias2[n + 1]; }
            }
            if (split) {
                atomicAdd(&C[(size_t)m0 * N + n],           acc[i][j][0] + b0);
                atomicAdd(&C[(size_t)m0 * N + n + 1],       acc[i][j][1] + b1);
                atomicAdd(&C[(size_t)(m0 + 8) * N + n],     acc[i][j][2] + b0);
                atomicAdd(&C[(size_t)(m0 + 8) * N + n + 1], acc[i][j][3] + b1);
            } else {
                C[(size_t)m0 * N + n]           = acc[i][j][0] + b0;
                C[(size_t)m0 * N + n + 1]       = acc[i][j][1] + b1;
                C[(size_t)(m0 + 8) * N + n]     = acc[i][j][2] + b0;
                C[(size_t)(m0 + 8) * N + n + 1] = acc[i][j][3] + b1;
            }
        }
    }
}

// ---------------------------------------------------------------------------
// Vocab GEMM: bf16 m16n8k16 MMA + 4-stage cp.async fp32 pipeline.
// logits[128, 50000] = o1[128,512] @ W_o2[50000,512]^T + b_o2
// ---------------------------------------------------------------------------
#define VG_LDS 24
#define VG_STAGEF (128 * VG_LDS)
#define VG_STAGEB (VG_STAGEF * 4)
#define VG_STAGES 4
#define VG_SMEM_BYTES (VG_STAGES * VG_STAGEB * 2)   // 98304

__device__ __forceinline__ void vg_prefetch(
    int s, int stage, const float* __restrict__ A, const float* __restrict__ W,
    int bn0, uint32_t sA, uint32_t sW)
{
    int ck = s * 16;
    int tid = threadIdx.x;
#pragma unroll
    for (int i = 0; i < 2; i++) {
        int slot = i * 256 + tid;
        int row = slot >> 2;
        int c4 = (slot & 3) << 2;
        uint32_t soff = (uint32_t)(stage * VG_STAGEB + (row * VG_LDS + c4) * 4);
        asm volatile("cp.async.cg.shared.global [%0], [%1], 16;"
                     :: "r"(sA + soff), "l"(A + row * 512 + ck + c4) : "memory");
        int nrow = bn0 + row;
        if (nrow < Vv)
            asm volatile("cp.async.cg.shared.global [%0], [%1], 16;"
                         :: "r"(sW + soff), "l"(W + (size_t)nrow * 512 + ck + c4) : "memory");
    }
    asm volatile("cp.async.commit_group;" ::: "memory");
}

__global__ __launch_bounds__(256) void vocab_gemm_mma(
    const float* __restrict__ A, const float* __restrict__ W,
    const float* __restrict__ bias, float* __restrict__ Cl)
{
    extern __shared__ __align__(16) float vgsm[];
    float* As = vgsm;
    float* Ws = vgsm + VG_STAGES * VG_STAGEF;

    int tid = threadIdx.x;
    int lane = tid & 31;
    int wid = tid >> 5;
    int wm = (wid & 1) * 64;
    int wn = (wid >> 1) * 32;
    int bn0 = blockIdx.x * 128;

    int grp = lane >> 2;
    int qid = lane & 3;

    uint32_t sA = smem_u32(As);
    uint32_t sW = smem_u32(Ws);

    if (bn0 + 128 > Vv) {
#pragma unroll
        for (int st = 0; st < VG_STAGES; st++)
            for (int slot = tid; slot < 512; slot += 256) {
                int row = slot >> 2;
                int c4 = (slot & 3) << 2;
                if (bn0 + row >= Vv)
                    *(float4*)&Ws[st * VG_STAGEF + row * VG_LDS + c4] =
                        make_float4(0.f, 0.f, 0.f, 0.f);
            }
        __syncthreads();
    }

    float acc[4][4][4];
#pragma unroll
    for (int i = 0; i < 4; i++)
#pragma unroll
        for (int j = 0; j < 4; j++)
#pragma unroll
            for (int r = 0; r < 4; r++) acc[i][j][r] = 0.0f;

    vg_prefetch(0, 0, A, W, bn0, sA, sW);
    vg_prefetch(1, 1, A, W, bn0, sA, sW);
    vg_prefetch(2, 2, A, W, bn0, sA, sW);

    for (int s = 0; s < 32; s++) {
        int stage = s & 3;
        if (s < 29) {
            vg_prefetch(s + 3, (s + 3) & 3, A, W, bn0, sA, sW);
            asm volatile("cp.async.wait_group 3;" ::: "memory");
        } else if (s == 29) {
            asm volatile("cp.async.wait_group 2;" ::: "memory");
        } else if (s == 30) {
            asm volatile("cp.async.wait_group 1;" ::: "memory");
        } else {
            asm volatile("cp.async.wait_group 0;" ::: "memory");
        }
        __syncthreads();

        const float* as = As + stage * VG_STAGEF;
        const float* ws = Ws + stage * VG_STAGEF;

        uint32_t af[4][4];
#pragma unroll
        for (int t = 0; t < 4; t++) {
            int r0 = wm + t * 16 + grp;
            const float* b0 = as + r0 * VG_LDS;
            const float* b1 = as + (r0 + 8) * VG_LDS;
            af[t][0] = cvt_bf2(*(const float2*)(b0 + 2 * qid));
            af[t][1] = cvt_bf2(*(const float2*)(b1 + 2 * qid));
            af[t][2] = cvt_bf2(*(const float2*)(b0 + 8 + 2 * qid));
            af[t][3] = cvt_bf2(*(const float2*)(b1 + 8 + 2 * qid));
        }
        uint32_t bf[4][2];
#pragma unroll
        for (int t = 0; t < 4; t++) {
            int n0 = wn + t * 8 + grp;
            const float* b = ws + n0 * VG_LDS;
            bf[t][0] = cvt_bf2(*(const float2*)(b + 2 * qid));
            bf[t][1] = cvt_bf2(*(const float2*)(b + 8 + 2 * qid));
        }
#pragma unroll
        for (int i = 0; i < 4; i++)
#pragma unroll
            for (int j = 0; j < 4; j++) {
                asm volatile(
                    "mma.sync.aligned.m16n8k16.row.col.f32.bf16.bf16.f32 "
                    "{%0,%1,%2,%3}, {%4,%5,%6,%7}, {%8,%9}, {%0,%1,%2,%3};"
                    : "+f"(acc[i][j][0]), "+f"(acc[i][j][1]),
                      "+f"(acc[i][j][2]), "+f"(acc[i][j][3])
                    : "r"(af[i][0]), "r"(af[i][1]), "r"(af[i][2]), "r"(af[i][3]),
                      "r"(bf[j][0]), "r"(bf[j][1]));
            }
        __syncthreads();
    }

#pragma unroll
    for (int i = 0; i < 4; i++) {
        int m0 = wm + i * 16 + grp;
#pragma unroll
        for (int j = 0; j < 4; j++) {
            int n = bn0 + wn + j * 8 + 2 * qid;
            if (n < Vv) {
                float2 b2 = *(const float2*)&bias[n];
                float2 v0 = make_float2(acc[i][j][0] + b2.x, acc[i][j][1] + b2.y);
                float2 v1 = make_float2(acc[i][j][2] + b2.x, acc[i][j][3] + b2.y);
                *(float2*)&Cl[(size_t)m0 * Vv + n] = v0;
                *(float2*)&Cl[(size_t)(m0 + 8) * Vv + n] = v1;
            }
        }
    }
}

// ---------------------------------------------------------------------------
// LSTM elementwise (float4 vectorized)
// ---------------------------------------------------------------------------
__global__ void lstm_kernel(const float* __restrict__ gates, const float* __restrict__ c0,
                            float* __restrict__ out) {
    int q = blockIdx.x * blockDim.x + threadIdx.x;
    if (q >= Bb * Hh / 4) return;
    int b = q >> 7;
    int h4 = (q & 127) << 2;
    const float* g = gates + (size_t)b * 4 * Hh;
    float4 gi = *(const float4*)&g[h4];
    float4 gf = *(const float4*)&g[512 + h4];
    float4 gg = *(const float4*)&g[1024 + h4];
    float4 go = *(const float4*)&g[1536 + h4];
    float4 cp = *(const float4*)&c0[(size_t)b * Hh + h4];
    float4 c, hh;
    c.x = sigmoid_fast(gf.x) * cp.x + sigmoid_fast(gi.x) * tanhf(gg.x);
    c.y = sigmoid_fast(gf.y) * cp.y + sigmoid_fast(gi.y) * tanhf(gg.y);
    c.z = sigmoid_fast(gf.z) * cp.z + sigmoid_fast(gi.z) * tanhf(gg.z);
    c.w = sigmoid_fast(gf.w) * cp.w + sigmoid_fast(gi.w) * tanhf(gg.w);
    hh.x = sigmoid_fast(go.x) * tanhf(c.x);
    hh.y = sigmoid_fast(go.y) * tanhf(c.y);
    hh.z = sigmoid_fast(go.z) * tanhf(c.z);
    hh.w = sigmoid_fast(go.w) * tanhf(c.w);
    *(float4*)&out[OFF_H + (size_t)b * Hh + h4] = hh;
    *(float4*)&out[OFF_C + (size_t)b * Hh + h4] = c;
}

// ---------------------------------------------------------------------------
// Attention scores
// ---------------------------------------------------------------------------
__global__ __launch_bounds__(256) void scores_kernel(
    const float* __restrict__ ef, const float* __restrict__ dec,
    const float* __restrict__ vw, const float* __restrict__ Wc,
    const float* __restrict__ cov, float* __restrict__ scores)
{
    __shared__ __align__(16) float s_dec[H2];
    __shared__ __align__(16) float s_v[H2];
    __shared__ __align__(16) float s_wc[H2];
    int b = blockIdx.y;
    int tid = threadIdx.x;
    for (int i = tid; i < H2; i += 256) {
        s_dec[i] = dec[(size_t)b * H2 + i];
        s_v[i] = vw[i];
        s_wc[i] = Wc[i];
    }
    __syncthreads();

    int warp = tid >> 5, lane = tid & 31;
    int t = blockIdx.x * 8 + warp;
    float cv = cov[(size_t)b * Tt + t];
    const float* p = ef + ((size_t)b * Tt + t) * H2;

    float acc = 0.0f;
#pragma unroll
    for (int i = 0; i < 8; i++) {
        int n = i * 128 + lane * 4;
        float4 e4 = *(const float4*)(p + n);
        acc += tanh_fast(e4.x + s_dec[n]     + cv * s_wc[n])     * s_v[n];
        acc += tanh_fast(e4.y + s_dec[n + 1] + cv * s_wc[n + 1]) * s_v[n + 1];
        acc += tanh_fast(e4.z + s_dec[n + 2] + cv * s_wc[n + 2]) * s_v[n + 2];
        acc += tanh_fast(e4.w + s_dec[n + 3] + cv * s_wc[n + 3]) * s_v[n + 3];
    }
#pragma unroll
    for (int o = 16; o > 0; o >>= 1) acc += __shfl_down_sync(0xffffffffu, acc, o);
    if (lane == 0) scores[(size_t)b * Tt + t] = acc;
}

// ---------------------------------------------------------------------------
// Fused attention: softmax over T (+mask renorm +coverage), half of c_t,
// partial p_gen dot (atomicAdd into g_pgacc).
// grid = (2, 128), 512 threads.
// ---------------------------------------------------------------------------
__global__ __launch_bounds__(512) void attn_fused_kernel(
    const float* __restrict__ scores, const float* __restrict__ mask,
    const float* __restrict__ cov, const float* __restrict__ eo,
    const float* __restrict__ x, const float* __restrict__ Wpg,
    float* __restrict__ pgacc, float* __restrict__ out)
{
    __shared__ float red[512];
    __shared__ float sa[Tt];

    int b = blockIdx.y, hx = blockIdx.x, tid = threadIdx.x;

    float s = (tid < Tt) ? scores[(size_t)b * Tt + tid] : -1e30f;
    red[tid] = s; __syncthreads();
    for (int st = 256; st > 0; st >>= 1) {
        if (tid < st) red[tid] = fmaxf(red[tid], red[tid + st]);
        __syncthreads();
    }
    float m = red[0]; __syncthreads();

    float e = (tid < Tt) ? __expf(s - m) : 0.0f;
    red[tid] = e; __syncthreads();
    for (int st = 256; st > 0; st >>= 1) {
        if (tid < st) red[tid] += red[tid + st];
        __syncthreads();
    }
    float S = red[0]; __syncthreads();

    float a = (tid < Tt) ? (e / S) * mask[(size_t)b * Tt + tid] : 0.0f;
    red[tid] = a; __syncthreads();
    for (int st = 256; st > 0; st >>= 1) {
        if (tid < st) red[tid] += red[tid + st];
        __syncthreads();
    }
    float S2 = red[0] + 1e-12f;

    float attn = a / S2;
    if (tid < Tt) {
        sa[tid] = attn;
        if (hx == 0) {
            out[OFF_ATTN + (size_t)b * Tt + tid] = attn;
            out[OFF_COV  + (size_t)b * Tt + tid] = cov[(size_t)b * Tt + tid] + attn;
        }
    }
    __syncthreads();

    int n = hx * 512 + tid;
    const float* p = eo + (size_t)b * Tt * H2 + n;
    float acc = 0.0f;
#pragma unroll 16
    for (int t = 0; t < Tt; t++) acc += sa[t] * p[(size_t)t * H2];
    out[OFF_CT + (size_t)b * H2 + n] = acc;

    float pacc = acc * Wpg[n];
    if (hx == 0) {
        pacc += out[OFF_H + (size_t)b * Hh + tid] * Wpg[1024 + tid];
        if (tid < Ee) pacc += x[(size_t)b * Ee + tid] * Wpg[2048 + tid];
    } else {
        pacc += out[OFF_C + (size_t)b * Hh + tid] * Wpg[1536 + tid];
    }
    red[tid] = pacc; __syncthreads();
    for (int st = 256; st > 0; st >>= 1) {
        if (tid < st) red[tid] += red[tid + st];
        __syncthreads();
    }
    if (tid == 0) atomicAdd(&pgacc[b], red[0]);
}

// ---------------------------------------------------------------------------
// Fused vocab softmax (online, float4) + p_gen finalize + pointer scatter
// + scratch-accumulator re-zero (keeps call-start invariant: all zeroed).
// grid = 128, 1024 threads. Vv = 50000 = 12500 float4 exactly.
// ---------------------------------------------------------------------------
__global__ __launch_bounds__(1024) void vsoftmax_scatter_kernel(
    const float* __restrict__ logits, const int* __restrict__ ebev,
    const float* __restrict__ pgacc, const float* __restrict__ bpg,
    float* __restrict__ gx, float* __restrict__ ggates,
    float* __restrict__ gdec, float* __restrict__ go1, float* __restrict__ gpg,
    float* __restrict__ out)
{
    __shared__ float smx[1024];
    __shared__ float ssm[1024];
    int b = blockIdx.x, tid = threadIdx.x;
    const float4* L4 = (const float4*)(logits + (size_t)b * Vv);

    float m = -1e30f, s = 0.0f;
    for (int j = tid; j < Vv / 4; j += 1024) {
        float4 v = L4[j];
        float m4 = fmaxf(fmaxf(v.x, v.y), fmaxf(v.z, v.w));
        float nm = fmaxf(m, m4);
        s = s * __expf(m - nm) + __expf(v.x - nm) + __expf(v.y - nm)
          + __expf(v.z - nm) + __expf(v.w - nm);
        m = nm;
    }
    smx[tid] = m; ssm[tid] = s; __syncthreads();
    for (int st = 512; st > 0; st >>= 1) {
        if (tid < st) {
            float m2 = smx[tid + st], s2 = ssm[tid + st];
            float m1 = smx[tid],      s1 = ssm[tid];
            float nm = fmaxf(m1, m2);
            ssm[tid] = s1 * __expf(m1 - nm) + s2 * __expf(m2 - nm);
            smx[tid] = nm;
        }
        __syncthreads();
    }
    float M = smx[0], S = ssm[0];

    float pg = sigmoid_fast(pgacc[b] + bpg[0]);
    if (tid == 0) out[OFF_PGEN + b] = pg;

    float scale = pg / S;
    float4* F4 = (float4*)(out + (size_t)b * Vv);
    for (int j = tid; j < Vv / 4; j += 1024) {
        float4 v = L4[j];
        float4 w;
        w.x = __expf(v.x - M) * scale;
        w.y = __expf(v.y - M) * scale;
        w.z = __expf(v.z - M) * scale;
        w.w = __expf(v.w - M) * scale;
        F4[j] = w;
    }
    __syncthreads();

    // scatter
    if (tid < Tt) {
        float a = out[OFF_ATTN + (size_t)b * Tt + tid];
        atomicAdd(&out[(size_t)b * Vv + ebev[(size_t)b * Tt + tid]], (1.0f - pg) * a);
    }

    // re-zero atomic accumulators for the next call (grid-stride)
    int gi = b * 1024 + tid;
    int gs = 128 * 1024;
    for (int j = gi; j < Bb * Ee; j += gs) gx[j] = 0.0f;
    for (int j = gi; j < Bb * 4 * Hh; j += gs) ggates[j] = 0.0f;
    for (int j = gi; j < Bb * H2; j += gs) gdec[j] = 0.0f;
    for (int j = gi; j < Bb * Hh; j += gs) go1[j] = 0.0f;
    if (gi < Bb) gpg[gi] = 0.0f;
}

// ---------------------------------------------------------------------------
// Host launch
// ---------------------------------------------------------------------------
static void launch_small(const float* A1, int lda1, int K1, const float* W1, int ldw1,
                         const float* A2, int lda2, int K2, const float* W2, int ldw2,
                         const int* a2_idx,
                         const float* b1, const float* b2, float* C, int N, int kchunk)
{
    int steps = (K1 + K2) >> 4;
    int ky = (steps + kchunk - 1) / kchunk;
    dim3 grid(N / 128, ky);
    small_gemm_mma<<<grid, 256, SG_SMEM_BYTES>>>(
        A1, lda1, K1, W1, ldw1, A2, lda2, K2, W2, ldw2,
        a2_idx, b1, b2, C, N, kchunk, (ky > 1) ? 1 : 0);
}

extern "C" void kernel_launch(void* const* d_in, const int* in_sizes, int n_in,
                              void* d_out_v, int out_size)
{
    (void)in_sizes; (void)n_in; (void)out_size;
    const int*   y    = (const int*)  d_in[0];
    const float* h0   = (const float*)d_in[1];
    const float* c0   = (const float*)d_in[2];
    const float* ct1  = (const float*)d_in[3];
    const float* eo   = (const float*)d_in[4];
    const float* ef   = (const float*)d_in[5];
    const float* mask = (const float*)d_in[6];
    const int*   ebev = (const int*)  d_in[7];
    const float* cov  = (const float*)d_in[8];
    const float* emb  = (const float*)d_in[9];
    const float* W_c  = (const float*)d_in[10];
    const float* W_dp = (const float*)d_in[11];
    const float* b_dp = (const float*)d_in[12];
    const float* v_w  = (const float*)d_in[13];
    const float* W_xc = (const float*)d_in[14];
    const float* b_xc = (const float*)d_in[15];
    const float* W_ih = (const float*)d_in[16];
    const float* W_hh = (const float*)d_in[17];
    const float* b_ih = (const float*)d_in[18];
    const float* b_hh = (const float*)d_in[19];
    const float* W_pg = (const float*)d_in[20];
    const float* b_pg = (const float*)d_in[21];
    const float* W_o1 = (const float*)d_in[22];
    const float* b_o1 = (const float*)d_in[23];
    const float* W_o2 = (const float*)d_in[24];
    const float* b_o2 = (const float*)d_in[25];
    float* out = (float*)d_out_v;

    float *p_x, *p_gates, *p_dec, *p_scores, *p_o1, *p_logits, *p_pgacc;
    cudaGetSymbolAddress((void**)&p_x,      g_x);
    cudaGetSymbolAddress((void**)&p_gates,  g_gates);
    cudaGetSymbolAddress((void**)&p_dec,    g_decfea);
    cudaGetSymbolAddress((void**)&p_scores, g_scores);
    cudaGetSymbolAddress((void**)&p_o1,     g_o1);
    cudaGetSymbolAddress((void**)&p_logits, g_logits);
    cudaGetSymbolAddress((void**)&p_pgacc,  g_pgacc);

    cudaFuncSetAttribute(vocab_gemm_mma, cudaFuncAttributeMaxDynamicSharedMemorySize,
                         VG_SMEM_BYTES);
    cudaFuncSetAttribute(small_gemm_mma, cudaFuncAttributeMaxDynamicSharedMemorySize,
                         SG_SMEM_BYTES);

    // Accumulators are zero here (module-load init + re-zero in step 9 tail).

    // 1. x = [c_t_1 | emb[y]] @ W_xc^T + b_xc  (N=128, 72 steps -> grid (1,72))
    launch_small(ct1, H2, H2, W_xc, 1152,
                 emb, Ee, Ee, W_xc + 1024, 1152, y,
                 b_xc, nullptr, p_x, Ee, 1);

    // 2. gates = x @ W_ih^T + h0 @ W_hh^T + b_ih + b_hh  (N=2048, grid (16,8))
    launch_small(p_x, Ee, Ee, W_ih, Ee,
                 h0, Hh, Hh, W_hh, Hh, nullptr,
                 b_ih, b_hh, p_gates, 4 * Hh, 5);

    // 3. LSTM cell
    lstm_kernel<<<(Bb * Hh / 4 + 255) / 256, 256>>>(p_gates, c0, out);

    // 4. dec_fea = [h | c] @ W_dp^T + b_dp  (N=1024, grid (8,16))
    launch_small(out + OFF_H, Hh, Hh, W_dp, H2,
                 out + OFF_C, Hh, Hh, W_dp + 512, H2, nullptr,
                 b_dp, nullptr, p_dec, H2, 4);

    // 5. attention scores
    scores_kernel<<<dim3(Tt / 8, Bb), 256>>>(ef, p_dec, v_w, W_c, cov, p_scores);

    // 6. fused softmax + c_t halves + partial p_gen
    attn_fused_kernel<<<dim3(2, Bb), 512>>>(p_scores, mask, cov, eo, p_x, W_pg,
                                            p_pgacc, out);

    // 7. o1 = [h | c_t] @ W_o1^T + b_o1  (N=512, grid (4,32))
    launch_small(out + OFF_H, Hh, Hh, W_o1, 3 * Hh,
                 out + OFF_CT, H2, H2, W_o1 + 512, 3 * Hh, nullptr,
                 b_o1, nullptr, p_o1, Hh, 3);

    // 8. logits via bf16 m16n8k16 MMA GEMM, 4-stage cp.async pipeline
    vocab_gemm_mma<<<(Vv + 127) / 128, 256, VG_SMEM_BYTES>>>(p_o1, W_o2, b_o2, p_logits);

    // 9. fused vocab softmax + p_gen finalize + scatter + accumulator re-zero
    vsoftmax_scatter_kernel<<<Bb, 1024>>>(p_logits, ebev, p_pgacc, b_pg,
                                          p_x, p_gates, p_dec, p_o1, p_pgacc, out);
}